// round 2
// baseline (speedup 1.0000x reference)
#include <cuda_runtime.h>

#define BATCH 4
#define NPTS  8192
#define SPTS  2048
#define D1    128
#define D2    256
#define CIN   384
#define CMID  256
#define COUT  256
#define PTOT  (BATCH*NPTS)   // 32768

// ---------------- scratch (device globals; no allocation allowed) ----------
__device__ float g_f2t [BATCH*SPTS*D2];   // [B,S,D2]    8 MB
__device__ float g_feat[PTOT*CIN];        // [P,384]    48 MB (point-major)
__device__ float g_y1  [CMID*PTOT];       // [256,P]    32 MB
__device__ float g_y2  [COUT*PTOT];       // [256,P]    32 MB
__device__ int   g_idx [PTOT*3];
__device__ float g_w   [PTOT*3];
__device__ float g_bnA1[CMID], g_bnB1[CMID];
__device__ float g_bnA2[COUT], g_bnB2[COUT];

// ---------------- transpose feature2 [B,256,2048] -> [B,2048,256] ----------
__global__ void transpose_f2_kernel(const float* __restrict__ f2) {
    __shared__ float tile[32][33];
    int b  = blockIdx.z;
    int s0 = blockIdx.x * 32, d0 = blockIdx.y * 32;
    const float* src = f2 + (size_t)b * D2 * SPTS;
    #pragma unroll
    for (int i = 0; i < 32; i += 8)
        tile[threadIdx.y + i][threadIdx.x] =
            src[(size_t)(d0 + threadIdx.y + i) * SPTS + s0 + threadIdx.x];
    __syncthreads();
    float* dst = g_f2t + (size_t)b * SPTS * D2;
    #pragma unroll
    for (int i = 0; i < 32; i += 8)
        dst[(size_t)(s0 + threadIdx.y + i) * D2 + d0 + threadIdx.x] =
            tile[threadIdx.x][threadIdx.y + i];
}

// ---------------- copy feature1 [B,128,8192] -> feat[:,256:384] ------------
__global__ void copy_f1_kernel(const float* __restrict__ f1) {
    __shared__ float tile[32][33];
    int b  = blockIdx.z;
    int n0 = blockIdx.x * 32, d0 = blockIdx.y * 32;
    const float* src = f1 + (size_t)b * D1 * NPTS;
    #pragma unroll
    for (int i = 0; i < 32; i += 8)
        tile[threadIdx.y + i][threadIdx.x] =
            src[(size_t)(d0 + threadIdx.y + i) * NPTS + n0 + threadIdx.x];
    __syncthreads();
    #pragma unroll
    for (int i = 0; i < 32; i += 8)
        g_feat[(size_t)(b * NPTS + n0 + threadIdx.y + i) * CIN + D2 + d0 + threadIdx.x] =
            tile[threadIdx.x][threadIdx.y + i];
}

// ---------------- 3-NN: one thread per query point -------------------------
__global__ void __launch_bounds__(256) knn_kernel(const float* __restrict__ pos1,
                                                  const float* __restrict__ pos2) {
    __shared__ float sx[SPTS], sy[SPTS], sz[SPTS], sq[SPTS];
    int b = blockIdx.y;
    const float* p2 = pos2 + (size_t)b * 3 * SPTS;
    for (int i = threadIdx.x; i < SPTS; i += blockDim.x) {
        float x = p2[i], y = p2[SPTS + i], z = p2[2 * SPTS + i];
        sx[i] = x; sy[i] = y; sz[i] = z;
        sq[i] = x * x + y * y + z * z;
    }
    __syncthreads();
    int n = blockIdx.x * blockDim.x + threadIdx.x;
    const float* p1 = pos1 + (size_t)b * 3 * NPTS;
    float x = p1[n], y = p1[NPTS + n], z = p1[2 * NPTS + n];
    float sq1 = x * x + y * y + z * z;
    float b0 = 3.4e38f, b1 = 3.4e38f, b2 = 3.4e38f;
    int   i0 = 0, i1 = 0, i2 = 0;
    for (int s = 0; s < SPTS; s++) {
        float dot = x * sx[s] + y * sy[s] + z * sz[s];
        float d   = sq1 - 2.0f * dot + sq[s];
        if (d < b2) {
            if (d < b1) {
                if (d < b0) { b2 = b1; i2 = i1; b1 = b0; i1 = i0; b0 = d; i0 = s; }
                else        { b2 = b1; i2 = i1; b1 = d;  i1 = s; }
            } else          { b2 = d;  i2 = s; }
        }
    }
    float w0 = 1.0f / fmaxf(b0, 1e-10f);
    float w1 = 1.0f / fmaxf(b1, 1e-10f);
    float w2 = 1.0f / fmaxf(b2, 1e-10f);
    float ws = w0 + w1 + w2;
    int p = b * NPTS + n;
    g_w[p * 3 + 0] = w0 / ws;  g_w[p * 3 + 1] = w1 / ws;  g_w[p * 3 + 2] = w2 / ws;
    g_idx[p * 3 + 0] = i0;     g_idx[p * 3 + 1] = i1;     g_idx[p * 3 + 2] = i2;
}

// ---------------- weighted gather-interp -> feat[:,0:256] ------------------
__global__ void __launch_bounds__(256) interp_kernel() {
    int p = blockIdx.x;
    int b = p >> 13;
    int i0 = g_idx[p * 3 + 0], i1 = g_idx[p * 3 + 1], i2 = g_idx[p * 3 + 2];
    float w0 = g_w[p * 3 + 0], w1 = g_w[p * 3 + 1], w2 = g_w[p * 3 + 2];
    const float* r0 = g_f2t + (size_t)(b * SPTS + i0) * D2;
    const float* r1 = g_f2t + (size_t)(b * SPTS + i1) * D2;
    const float* r2 = g_f2t + (size_t)(b * SPTS + i2) * D2;
    int d = threadIdx.x;
    g_feat[(size_t)p * CIN + d] = w0 * r0[d] + w1 * r1[d] + w2 * r2[d];
}

// ---------------- GEMM1 (NT): y1[m,p] = sum_k W1[m,k]*feat[p,k] + b1[m] ----
__global__ void __launch_bounds__(256) gemm1_kernel(const float* __restrict__ W,
                                                    const float* __restrict__ bias) {
    __shared__ float sA[8][132];
    __shared__ float sB[8][132];
    int m0 = blockIdx.y * 128, p0 = blockIdx.x * 128;
    int tid = threadIdx.x;
    int lr = tid >> 1;            // 0..127
    int lk = (tid & 1) * 4;       // 0 or 4
    int tm = tid >> 4, tn = tid & 15;
    float acc[8][8] = {};
    for (int k0 = 0; k0 < CIN; k0 += 8) {
        float4 av = *(const float4*)&W[(size_t)(m0 + lr) * CIN + k0 + lk];
        float4 bv = *(const float4*)&g_feat[(size_t)(p0 + lr) * CIN + k0 + lk];
        __syncthreads();
        sA[lk + 0][lr] = av.x; sA[lk + 1][lr] = av.y; sA[lk + 2][lr] = av.z; sA[lk + 3][lr] = av.w;
        sB[lk + 0][lr] = bv.x; sB[lk + 1][lr] = bv.y; sB[lk + 2][lr] = bv.z; sB[lk + 3][lr] = bv.w;
        __syncthreads();
        #pragma unroll
        for (int kk = 0; kk < 8; kk++) {
            float a[8], bb[8];
            #pragma unroll
            for (int i = 0; i < 8; i++) a[i]  = sA[kk][tm * 8 + i];
            #pragma unroll
            for (int j = 0; j < 8; j++) bb[j] = sB[kk][tn * 8 + j];
            #pragma unroll
            for (int i = 0; i < 8; i++)
                #pragma unroll
                for (int j = 0; j < 8; j++) acc[i][j] += a[i] * bb[j];
        }
    }
    #pragma unroll
    for (int i = 0; i < 8; i++) {
        float bi = bias[m0 + tm * 8 + i];
        #pragma unroll
        for (int j = 0; j < 8; j++)
            g_y1[(size_t)(m0 + tm * 8 + i) * PTOT + p0 + tn * 8 + j] = acc[i][j] + bi;
    }
}

// ---------------- per-channel BN stats over [C, P] rows --------------------
__global__ void __launch_bounds__(256) stats_kernel(int which,
                                                    const float* __restrict__ g,
                                                    const float* __restrict__ beta) {
    const float* y = which ? g_y2 : g_y1;
    int c = blockIdx.x;
    const float4* row = (const float4*)(y + (size_t)c * PTOT);
    float s = 0.f, s2 = 0.f;
    for (int i = threadIdx.x; i < PTOT / 4; i += 256) {
        float4 v = row[i];
        s  += v.x + v.y + v.z + v.w;
        s2 += v.x * v.x + v.y * v.y + v.z * v.z + v.w * v.w;
    }
    __shared__ float rs[256], rs2[256];
    rs[threadIdx.x] = s; rs2[threadIdx.x] = s2;
    __syncthreads();
    for (int off = 128; off > 0; off >>= 1) {
        if (threadIdx.x < off) {
            rs[threadIdx.x]  += rs[threadIdx.x + off];
            rs2[threadIdx.x] += rs2[threadIdx.x + off];
        }
        __syncthreads();
    }
    if (threadIdx.x == 0) {
        float mean = rs[0] / (float)PTOT;
        float var  = rs2[0] / (float)PTOT - mean * mean;
        float rstd = rsqrtf(var + 1e-5f);
        float A = g[c] * rstd;
        float B = beta[c] - mean * A;
        if (which) { g_bnA2[c] = A; g_bnB2[c] = B; }
        else       { g_bnA1[c] = A; g_bnB1[c] = B; }
    }
}

// --------- GEMM2 (NN): y2[m,p] = sum_k W2[m,k]*relu(bn1(y1[k,p])) + b2[m] --
__global__ void __launch_bounds__(256) gemm2_kernel(const float* __restrict__ W,
                                                    const float* __restrict__ bias) {
    __shared__ float sA[8][132];
    __shared__ float sB[8][132];
    int m0 = blockIdx.y * 128, p0 = blockIdx.x * 128;
    int tid = threadIdx.x;
    int lr = tid >> 1;
    int lk = (tid & 1) * 4;
    int kr = tid >> 5;            // 0..7
    int pq = (tid & 31) * 4;      // 0..124
    int tm = tid >> 4, tn = tid & 15;
    float acc[8][8] = {};
    for (int k0 = 0; k0 < CMID; k0 += 8) {
        float4 av = *(const float4*)&W[(size_t)(m0 + lr) * CMID + k0 + lk];
        float4 bv = *(const float4*)&g_y1[(size_t)(k0 + kr) * PTOT + p0 + pq];
        float A = g_bnA1[k0 + kr], B = g_bnB1[k0 + kr];
        bv.x = fmaxf(bv.x * A + B, 0.f);
        bv.y = fmaxf(bv.y * A + B, 0.f);
        bv.z = fmaxf(bv.z * A + B, 0.f);
        bv.w = fmaxf(bv.w * A + B, 0.f);
        __syncthreads();
        sA[lk + 0][lr] = av.x; sA[lk + 1][lr] = av.y; sA[lk + 2][lr] = av.z; sA[lk + 3][lr] = av.w;
        *(float4*)&sB[kr][pq] = bv;
        __syncthreads();
        #pragma unroll
        for (int kk = 0; kk < 8; kk++) {
            float a[8], bb[8];
            #pragma unroll
            for (int i = 0; i < 8; i++) a[i]  = sA[kk][tm * 8 + i];
            #pragma unroll
            for (int j = 0; j < 8; j++) bb[j] = sB[kk][tn * 8 + j];
            #pragma unroll
            for (int i = 0; i < 8; i++)
                #pragma unroll
                for (int j = 0; j < 8; j++) acc[i][j] += a[i] * bb[j];
        }
    }
    #pragma unroll
    for (int i = 0; i < 8; i++) {
        float bi = bias[m0 + tm * 8 + i];
        #pragma unroll
        for (int j = 0; j < 8; j++)
            g_y2[(size_t)(m0 + tm * 8 + i) * PTOT + p0 + tn * 8 + j] = acc[i][j] + bi;
    }
}

// ---------------- final: BN2 + ReLU, permute [C,P] -> [B,C,N] --------------
__global__ void __launch_bounds__(256) final_kernel(float* __restrict__ out) {
    int idx = (blockIdx.x * 256 + threadIdx.x) * 4;   // flat [b][o][n] index
    int b   = idx >> 21;
    int rem = idx & ((1 << 21) - 1);
    int o   = rem >> 13;
    int n   = rem & 8191;
    float4 v = *(const float4*)&g_y2[(size_t)o * PTOT + b * NPTS + n];
    float A = g_bnA2[o], B = g_bnB2[o];
    v.x = fmaxf(v.x * A + B, 0.f);
    v.y = fmaxf(v.y * A + B, 0.f);
    v.z = fmaxf(v.z * A + B, 0.f);
    v.w = fmaxf(v.w * A + B, 0.f);
    *(float4*)&out[idx] = v;
}

// ---------------------------------------------------------------------------
extern "C" void kernel_launch(void* const* d_in, const int* in_sizes, int n_in,
                              void* d_out, int out_size) {
    const float* pos1  = (const float*)d_in[0];
    const float* pos2  = (const float*)d_in[1];
    const float* feat1 = (const float*)d_in[2];
    const float* feat2 = (const float*)d_in[3];
    const float* W1    = (const float*)d_in[4];
    const float* b1    = (const float*)d_in[5];
    const float* g1    = (const float*)d_in[6];
    const float* be1   = (const float*)d_in[7];
    const float* W2    = (const float*)d_in[8];
    const float* b2    = (const float*)d_in[9];
    const float* g2    = (const float*)d_in[10];
    const float* be2   = (const float*)d_in[11];
    float* out = (float*)d_out;

    transpose_f2_kernel<<<dim3(SPTS / 32, D2 / 32, BATCH), dim3(32, 8)>>>(feat2);
    copy_f1_kernel<<<dim3(NPTS / 32, D1 / 32, BATCH), dim3(32, 8)>>>(feat1);
    knn_kernel<<<dim3(NPTS / 256, BATCH), 256>>>(pos1, pos2);
    interp_kernel<<<PTOT, 256>>>();
    gemm1_kernel<<<dim3(PTOT / 128, CMID / 128), 256>>>(W1, b1);
    stats_kernel<<<CMID, 256>>>(0, g1, be1);
    gemm2_kernel<<<dim3(PTOT / 128, COUT / 128), 256>>>(W2, b2);
    stats_kernel<<<COUT, 256>>>(1, g2, be2);
    final_kernel<<<(BATCH * COUT * NPTS) / (256 * 4), 256>>>(out);
}

// round 4
// speedup vs baseline: 1.8797x; 1.8797x over previous
#include <cuda_runtime.h>
#include <cuda_bf16.h>
#include <cstdint>

#define BATCH 4
#define NPTS  8192
#define SPTS  2048
#define D1    128
#define D2    256
#define CIN   384
#define CMID  256
#define COUT  256
#define PTOT  (BATCH*NPTS)   // 32768

// GEMM tiling
#define TM 128            // CTA channels
#define TN 128            // CTA points
#define KC 64             // K chunk (bf16 elems)
#define ROWB 144          // padded SMEM row bytes (72 bf16 elems) -> conflict-free
#define OFF_AH 0
#define OFF_AL 18432
#define OFF_BH 36864
#define OFF_BL 55296
#define SMEM_DYN 73728    // 4 tiles of 18432B; epilogue tile (67584B) reuses it

// ---------------- device scratch ----------------
__device__ float          g_f2t[BATCH*SPTS*D2];       // fp32 [B,S,D2]  8MB
__device__ __nv_bfloat16  g_Fh[(size_t)PTOT*CIN];     // feat hi 24MB
__device__ __nv_bfloat16  g_Fl[(size_t)PTOT*CIN];     // feat lo 24MB
__device__ float          g_y1[(size_t)PTOT*CMID];    // [P,256] 32MB
__device__ float          g_y2[(size_t)PTOT*COUT];    // [P,256] 32MB
__device__ __nv_bfloat16  g_W1h[CMID*CIN],  g_W1l[CMID*CIN];
__device__ __nv_bfloat16  g_W2h[COUT*CMID], g_W2l[COUT*CMID];
__device__ int            g_idx[PTOT*3];
__device__ float          g_w[PTOT*3];
__device__ float          g_s1[CMID], g_ss1[CMID], g_s2[COUT], g_ss2[COUT];
__device__ float          g_bnA1[CMID], g_bnB1[CMID], g_bnA2[COUT], g_bnB2[COUT];

// ---------------- bf16 mma.sync (sm_80+, runs on Blackwell tensor cores) ---
static __device__ __forceinline__ void mma16816(float* d, const uint32_t* a,
                                                uint32_t b0, uint32_t b1) {
    asm volatile(
        "mma.sync.aligned.m16n8k16.row.col.f32.bf16.bf16.f32 "
        "{%0,%1,%2,%3}, {%4,%5,%6,%7}, {%8,%9}, {%0,%1,%2,%3};"
        : "+f"(d[0]), "+f"(d[1]), "+f"(d[2]), "+f"(d[3])
        : "r"(a[0]), "r"(a[1]), "r"(a[2]), "r"(a[3]), "r"(b0), "r"(b1));
}

// ---------------- prep: weights -> bf16 hi/lo, zero BN partial sums --------
__global__ void prep_kernel(const float* __restrict__ W1, const float* __restrict__ W2) {
    int i = blockIdx.x * 256 + threadIdx.x;
    if (i < CMID * CIN) {
        float w = W1[i];
        __nv_bfloat16 h = __float2bfloat16(w);
        g_W1h[i] = h;
        g_W1l[i] = __float2bfloat16(w - __bfloat162float(h));
    }
    if (i < COUT * CMID) {
        float w = W2[i];
        __nv_bfloat16 h = __float2bfloat16(w);
        g_W2h[i] = h;
        g_W2l[i] = __float2bfloat16(w - __bfloat162float(h));
    }
    if (i < 256) { g_s1[i] = 0.f; g_ss1[i] = 0.f; g_s2[i] = 0.f; g_ss2[i] = 0.f; }
}

// ---------------- transpose feature2 [B,256,2048] -> fp32 [B,2048,256] -----
__global__ void transpose_f2_kernel(const float* __restrict__ f2) {
    __shared__ float tile[32][33];
    int b  = blockIdx.z;
    int s0 = blockIdx.x * 32, d0 = blockIdx.y * 32;
    const float* src = f2 + (size_t)b * D2 * SPTS;
    #pragma unroll
    for (int i = 0; i < 32; i += 8)
        tile[threadIdx.y + i][threadIdx.x] =
            src[(size_t)(d0 + threadIdx.y + i) * SPTS + s0 + threadIdx.x];
    __syncthreads();
    float* dst = g_f2t + (size_t)b * SPTS * D2;
    #pragma unroll
    for (int i = 0; i < 32; i += 8)
        dst[(size_t)(s0 + threadIdx.y + i) * D2 + d0 + threadIdx.x] =
            tile[threadIdx.x][threadIdx.y + i];
}

// ---------------- copy feature1 -> feat cols [256,384) as bf16 hi/lo -------
__global__ void copy_f1_kernel(const float* __restrict__ f1) {
    __shared__ float tile[32][33];
    int b  = blockIdx.z;
    int n0 = blockIdx.x * 32, d0 = blockIdx.y * 32;
    const float* src = f1 + (size_t)b * D1 * NPTS;
    #pragma unroll
    for (int i = 0; i < 32; i += 8)
        tile[threadIdx.y + i][threadIdx.x] =
            src[(size_t)(d0 + threadIdx.y + i) * NPTS + n0 + threadIdx.x];
    __syncthreads();
    #pragma unroll
    for (int i = 0; i < 32; i += 8) {
        float v = tile[threadIdx.x][threadIdx.y + i];
        size_t o = (size_t)(b * NPTS + n0 + threadIdx.y + i) * CIN + D2 + d0 + threadIdx.x;
        __nv_bfloat16 h = __float2bfloat16(v);
        g_Fh[o] = h;
        g_Fl[o] = __float2bfloat16(v - __bfloat162float(h));
    }
}

// ---------------- 3-NN ----------------
__global__ void __launch_bounds__(256) knn_kernel(const float* __restrict__ pos1,
                                                  const float* __restrict__ pos2) {
    __shared__ float sx[SPTS], sy[SPTS], sz[SPTS], sq[SPTS];
    int b = blockIdx.y;
    const float* p2 = pos2 + (size_t)b * 3 * SPTS;
    for (int i = threadIdx.x; i < SPTS; i += blockDim.x) {
        float x = p2[i], y = p2[SPTS + i], z = p2[2 * SPTS + i];
        sx[i] = x; sy[i] = y; sz[i] = z;
        sq[i] = x * x + y * y + z * z;
    }
    __syncthreads();
    int n = blockIdx.x * blockDim.x + threadIdx.x;
    const float* p1 = pos1 + (size_t)b * 3 * NPTS;
    float x = p1[n], y = p1[NPTS + n], z = p1[2 * NPTS + n];
    float sq1 = x * x + y * y + z * z;
    float b0 = 3.4e38f, b1 = 3.4e38f, b2 = 3.4e38f;
    int   i0 = 0, i1 = 0, i2 = 0;
    for (int s = 0; s < SPTS; s++) {
        float dot = x * sx[s] + y * sy[s] + z * sz[s];
        float d   = sq1 - 2.0f * dot + sq[s];
        if (d < b2) {
            if (d < b1) {
                if (d < b0) { b2 = b1; i2 = i1; b1 = b0; i1 = i0; b0 = d; i0 = s; }
                else        { b2 = b1; i2 = i1; b1 = d;  i1 = s; }
            } else          { b2 = d;  i2 = s; }
        }
    }
    float w0 = 1.0f / fmaxf(b0, 1e-10f);
    float w1 = 1.0f / fmaxf(b1, 1e-10f);
    float w2 = 1.0f / fmaxf(b2, 1e-10f);
    float ws = w0 + w1 + w2;
    int p = b * NPTS + n;
    g_w[p * 3 + 0] = w0 / ws;  g_w[p * 3 + 1] = w1 / ws;  g_w[p * 3 + 2] = w2 / ws;
    g_idx[p * 3 + 0] = i0;     g_idx[p * 3 + 1] = i1;     g_idx[p * 3 + 2] = i2;
}

// ---------------- interp -> feat cols [0,256) as bf16 hi/lo ----------------
__global__ void __launch_bounds__(256) interp_kernel() {
    int p = blockIdx.x;
    int b = p >> 13;
    int i0 = g_idx[p * 3 + 0], i1 = g_idx[p * 3 + 1], i2 = g_idx[p * 3 + 2];
    float w0 = g_w[p * 3 + 0], w1 = g_w[p * 3 + 1], w2 = g_w[p * 3 + 2];
    const float* r0 = g_f2t + (size_t)(b * SPTS + i0) * D2;
    const float* r1 = g_f2t + (size_t)(b * SPTS + i1) * D2;
    const float* r2 = g_f2t + (size_t)(b * SPTS + i2) * D2;
    int d = threadIdx.x;
    float v = w0 * r0[d] + w1 * r1[d] + w2 * r2[d];
    __nv_bfloat16 h = __float2bfloat16(v);
    size_t o = (size_t)p * CIN + d;
    g_Fh[o] = h;
    g_Fl[o] = __float2bfloat16(v - __bfloat162float(h));
}

// ---------------- split-bf16 tensor-core GEMM via mma.sync -----------------
// MODE 0: y1[P,256] = W1 @ feat^T + b1   (K=384, NC=6)
// MODE 1: y2[P,256] = W2 @ relu(bn1(y1))^T + b2 (K=256, NC=4; B built on the fly)
// Per CTA: 128 channels x 128 points. 8 warps of 64x32. K staged in chunks of 64.
template<int NC, int MODE>
__global__ void __launch_bounds__(256, 2) gemm_mma(const float* __restrict__ bias) {
    extern __shared__ __align__(16) char sm[];
    int tid = threadIdx.x;
    int w   = tid >> 5, l = tid & 31;
    int mw  = (w >> 2) * 64;        // warp channel offset
    int nw  = (w & 3) * 32;         // warp point offset
    int m0  = blockIdx.y * TM;
    int p0  = blockIdx.x * TN;

    const __nv_bfloat16* Ah_src = (MODE == 0) ? g_W1h : g_W2h;
    const __nv_bfloat16* Al_src = (MODE == 0) ? g_W1l : g_W2l;
    const int AK = (MODE == 0) ? CIN : CMID;

    float acc[4][4][4] = {};

    const uint32_t* smAh = (const uint32_t*)(sm + OFF_AH);
    const uint32_t* smAl = (const uint32_t*)(sm + OFF_AL);
    const uint32_t* smBh = (const uint32_t*)(sm + OFF_BH);
    const uint32_t* smBl = (const uint32_t*)(sm + OFF_BL);

    for (int c = 0; c < NC; ++c) {
        int kc = c * KC;
        if (c) __syncthreads();
        // --- stage A hi/lo: 128 rows x 64 bf16 (8x uint4 per row) ----------
        #pragma unroll
        for (int i = 0; i < 4; i++) {
            int t = i * 256 + tid;
            int r = t >> 3, sc = t & 7;
            uint32_t d = (uint32_t)r * ROWB + sc * 16;
            *(uint4*)(sm + OFF_AH + d) = *(const uint4*)(Ah_src + (size_t)(m0 + r) * AK + kc + sc * 8);
            *(uint4*)(sm + OFF_AL + d) = *(const uint4*)(Al_src + (size_t)(m0 + r) * AK + kc + sc * 8);
        }
        // --- stage B hi/lo: 128 point-rows x 64 bf16 -----------------------
        if (MODE == 0) {
            #pragma unroll
            for (int i = 0; i < 4; i++) {
                int t = i * 256 + tid;
                int r = t >> 3, sc = t & 7;
                uint32_t d = (uint32_t)r * ROWB + sc * 16;
                *(uint4*)(sm + OFF_BH + d) = *(const uint4*)(g_Fh + (size_t)(p0 + r) * CIN + kc + sc * 8);
                *(uint4*)(sm + OFF_BL + d) = *(const uint4*)(g_Fl + (size_t)(p0 + r) * CIN + kc + sc * 8);
            }
        } else {
            #pragma unroll
            for (int i = 0; i < 8; i++) {
                int t = i * 256 + tid;
                int r = t >> 4, sc = t & 15;
                float4 v  = *(const float4*)(g_y1   + (size_t)(p0 + r) * CMID + kc + sc * 4);
                float4 Ac = *(const float4*)(g_bnA1 + kc + sc * 4);
                float4 Bc = *(const float4*)(g_bnB1 + kc + sc * 4);
                float x0 = fmaxf(v.x * Ac.x + Bc.x, 0.f);
                float x1 = fmaxf(v.y * Ac.y + Bc.y, 0.f);
                float x2 = fmaxf(v.z * Ac.z + Bc.z, 0.f);
                float x3 = fmaxf(v.w * Ac.w + Bc.w, 0.f);
                __nv_bfloat16 h0 = __float2bfloat16(x0), h1 = __float2bfloat16(x1);
                __nv_bfloat16 h2 = __float2bfloat16(x2), h3 = __float2bfloat16(x3);
                __nv_bfloat16 l0 = __float2bfloat16(x0 - __bfloat162float(h0));
                __nv_bfloat16 l1 = __float2bfloat16(x1 - __bfloat162float(h1));
                __nv_bfloat16 l2 = __float2bfloat16(x2 - __bfloat162float(h2));
                __nv_bfloat16 l3 = __float2bfloat16(x3 - __bfloat162float(h3));
                uint2 hv, lv;
                hv.x = (uint32_t)__bfloat16_as_ushort(h0) | ((uint32_t)__bfloat16_as_ushort(h1) << 16);
                hv.y = (uint32_t)__bfloat16_as_ushort(h2) | ((uint32_t)__bfloat16_as_ushort(h3) << 16);
                lv.x = (uint32_t)__bfloat16_as_ushort(l0) | ((uint32_t)__bfloat16_as_ushort(l1) << 16);
                lv.y = (uint32_t)__bfloat16_as_ushort(l2) | ((uint32_t)__bfloat16_as_ushort(l3) << 16);
                uint32_t d = (uint32_t)r * ROWB + sc * 8;
                *(uint2*)(sm + OFF_BH + d) = hv;
                *(uint2*)(sm + OFF_BL + d) = lv;
            }
        }
        __syncthreads();
        // --- compute: 4 k16 steps ------------------------------------------
        #pragma unroll
        for (int kk = 0; kk < 4; kk++) {
            int kw = kk * 8 + (l & 3);              // word offset in 36-word row
            uint32_t ah[4][4], al[4][4];
            #pragma unroll
            for (int mi = 0; mi < 4; mi++) {
                int rm = mw + mi * 16 + (l >> 2);
                ah[mi][0] = smAh[rm * 36 + kw];
                ah[mi][1] = smAh[(rm + 8) * 36 + kw];
                ah[mi][2] = smAh[rm * 36 + kw + 4];
                ah[mi][3] = smAh[(rm + 8) * 36 + kw + 4];
                al[mi][0] = smAl[rm * 36 + kw];
                al[mi][1] = smAl[(rm + 8) * 36 + kw];
                al[mi][2] = smAl[rm * 36 + kw + 4];
                al[mi][3] = smAl[(rm + 8) * 36 + kw + 4];
            }
            #pragma unroll
            for (int ni = 0; ni < 4; ni++) {
                int rn = nw + ni * 8 + (l >> 2);
                uint32_t bh0 = smBh[rn * 36 + kw], bh1 = smBh[rn * 36 + kw + 4];
                uint32_t bl0 = smBl[rn * 36 + kw], bl1 = smBl[rn * 36 + kw + 4];
                #pragma unroll
                for (int mi = 0; mi < 4; mi++) {
                    mma16816(acc[mi][ni], ah[mi], bh0, bh1);
                    mma16816(acc[mi][ni], ah[mi], bl0, bl1);
                    mma16816(acc[mi][ni], al[mi], bh0, bh1);
                }
            }
        }
    }

    // --- epilogue: acc -> SMEM tile [128p][132c], then stats + global ------
    __syncthreads();
    float* tile = (float*)sm;
    #pragma unroll
    for (int mi = 0; mi < 4; mi++) {
        int c_ = mw + mi * 16 + (l >> 2);
        #pragma unroll
        for (int ni = 0; ni < 4; ni++) {
            int p_ = nw + ni * 8 + (l & 3) * 2;
            tile[p_ * 132 + c_]            = acc[mi][ni][0];
            tile[(p_ + 1) * 132 + c_]      = acc[mi][ni][1];
            tile[p_ * 132 + c_ + 8]        = acc[mi][ni][2];
            tile[(p_ + 1) * 132 + c_ + 8]  = acc[mi][ni][3];
        }
    }
    __syncthreads();

    float* ydst = (MODE == 0) ? g_y1 : g_y2;
    float* gs   = (MODE == 0) ? g_s1 : g_s2;
    float* gss  = (MODE == 0) ? g_ss1 : g_ss2;

    // stats: thread -> (channel, half of points)
    {
        int c = tid & 127;
        int r0 = (tid >> 7) * 64;
        float bi = bias[m0 + c];
        float s = 0.f, s2 = 0.f;
        #pragma unroll 4
        for (int p = 0; p < 64; p++) {
            float v = tile[(r0 + p) * 132 + c] + bi;
            s += v; s2 += v * v;
        }
        atomicAdd(&gs[m0 + c], s);
        atomicAdd(&gss[m0 + c], s2);
    }
    // coalesced global write (+bias)
    #pragma unroll
    for (int i = 0; i < 16; i++) {
        int t = i * 256 + tid;
        int p = t >> 5, g = t & 31;
        float4 v  = *(const float4*)&tile[p * 132 + g * 4];
        float4 bb = *(const float4*)&bias[m0 + g * 4];
        v.x += bb.x; v.y += bb.y; v.z += bb.z; v.w += bb.w;
        *(float4*)&ydst[(size_t)(p0 + p) * 256 + m0 + g * 4] = v;
    }
}

// ---------------- BN finalize ----------------
__global__ void bnfin_kernel(int which, const float* __restrict__ g,
                             const float* __restrict__ beta) {
    int c = threadIdx.x;
    float s  = which ? g_s2[c]  : g_s1[c];
    float ss = which ? g_ss2[c] : g_ss1[c];
    float mean = s / (float)PTOT;
    float var  = ss / (float)PTOT - mean * mean;
    float A = g[c] * rsqrtf(var + 1e-5f);
    float B = beta[c] - mean * A;
    if (which) { g_bnA2[c] = A; g_bnB2[c] = B; }
    else       { g_bnA1[c] = A; g_bnB1[c] = B; }
}

// ---------------- final: BN2+ReLU + transpose [P,256] -> out [B,256,N] -----
__global__ void final_kernel(float* __restrict__ out) {
    __shared__ float tile[32][33];
    int p0 = blockIdx.x * 32, c0 = blockIdx.y * 32;
    int tx = threadIdx.x, ty = threadIdx.y;
    int c = c0 + tx;
    float A = g_bnA2[c], B = g_bnB2[c];
    #pragma unroll
    for (int i = 0; i < 32; i += 8) {
        float v = g_y2[(size_t)(p0 + ty + i) * 256 + c];
        tile[ty + i][tx] = fmaxf(v * A + B, 0.f);
    }
    __syncthreads();
    int b = p0 >> 13;
    int n0 = p0 & (NPTS - 1);
    #pragma unroll
    for (int i = 0; i < 32; i += 8)
        out[(size_t)b * COUT * NPTS + (size_t)(c0 + ty + i) * NPTS + n0 + tx] =
            tile[tx][ty + i];
}

// ---------------------------------------------------------------------------
extern "C" void kernel_launch(void* const* d_in, const int* in_sizes, int n_in,
                              void* d_out, int out_size) {
    const float* pos1  = (const float*)d_in[0];
    const float* pos2  = (const float*)d_in[1];
    const float* feat1 = (const float*)d_in[2];
    const float* feat2 = (const float*)d_in[3];
    const float* W1    = (const float*)d_in[4];
    const float* b1    = (const float*)d_in[5];
    const float* g1    = (const float*)d_in[6];
    const float* be1   = (const float*)d_in[7];
    const float* W2    = (const float*)d_in[8];
    const float* b2    = (const float*)d_in[9];
    const float* g2    = (const float*)d_in[10];
    const float* be2   = (const float*)d_in[11];
    float* out = (float*)d_out;

    cudaFuncSetAttribute(gemm_mma<6, 0>, cudaFuncAttributeMaxDynamicSharedMemorySize, SMEM_DYN);
    cudaFuncSetAttribute(gemm_mma<4, 1>, cudaFuncAttributeMaxDynamicSharedMemorySize, SMEM_DYN);

    prep_kernel<<<(CMID * CIN + 255) / 256, 256>>>(W1, W2);
    transpose_f2_kernel<<<dim3(SPTS / 32, D2 / 32, BATCH), dim3(32, 8)>>>(feat2);
    knn_kernel<<<dim3(NPTS / 256, BATCH), 256>>>(pos1, pos2);
    interp_kernel<<<PTOT, 256>>>();
    copy_f1_kernel<<<dim3(NPTS / 32, D1 / 32, BATCH), dim3(32, 8)>>>(feat1);
    gemm_mma<6, 0><<<dim3(PTOT / TN, CMID / TM), 256, SMEM_DYN>>>(b1);
    bnfin_kernel<<<1, 256>>>(0, g1, be1);
    gemm_mma<4, 1><<<dim3(PTOT / TN, COUT / TM), 256, SMEM_DYN>>>(b2);
    bnfin_kernel<<<1, 256>>>(1, g2, be2);
    final_kernel<<<dim3(PTOT / 32, COUT / 32), dim3(32, 8)>>>(out);
}

// round 6
// speedup vs baseline: 1.9600x; 1.0427x over previous
#include <cuda_runtime.h>
#include <cuda_bf16.h>
#include <cstdint>

#define BATCH 4
#define NPTS  8192
#define SPTS  2048
#define D1    128
#define D2    256
#define CIN   384
#define CMID  256
#define COUT  256
#define PTOT  (BATCH*NPTS)   // 32768

#define TM 128
#define TN 128
#define KC 64
#define ROWB 144          // padded SMEM row bytes -> conflict-free ldmatrix
#define OFF_AH 0
#define OFF_AL 18432
#define OFF_BH 36864
#define OFF_BL 55296
#define SMEM_DYN 73728

// ---------------- device scratch ----------------
__device__ float          g_f2t[BATCH*SPTS*D2];
__device__ __nv_bfloat16  g_Fh[(size_t)PTOT*CIN];
__device__ __nv_bfloat16  g_Fl[(size_t)PTOT*CIN];
__device__ float          g_y1[(size_t)PTOT*CMID];
__device__ float          g_y2[(size_t)PTOT*COUT];
__device__ __nv_bfloat16  g_B1h[(size_t)PTOT*CMID];  // relu(bn1(y1)) hi
__device__ __nv_bfloat16  g_B1l[(size_t)PTOT*CMID];  // relu(bn1(y1)) lo
__device__ __nv_bfloat16  g_W1h[CMID*CIN],  g_W1l[CMID*CIN];
__device__ __nv_bfloat16  g_W2h[COUT*CMID], g_W2l[COUT*CMID];
__device__ int            g_idx[PTOT*3];
__device__ float          g_w[PTOT*3];
__device__ float          g_s1[CMID], g_ss1[CMID], g_s2[COUT], g_ss2[COUT];
__device__ float          g_bnA1[CMID], g_bnB1[CMID], g_bnA2[COUT], g_bnB2[COUT];

// ---------------- asm helpers ----------------
static __device__ __forceinline__ uint32_t smem_u32(const void* p) {
    uint32_t a;
    asm("{ .reg .u64 t; cvta.to.shared.u64 t, %1; cvt.u32.u64 %0, t; }" : "=r"(a) : "l"(p));
    return a;
}
static __device__ __forceinline__ void mma16816(float* d, const uint32_t* a,
                                                uint32_t b0, uint32_t b1) {
    asm volatile(
        "mma.sync.aligned.m16n8k16.row.col.f32.bf16.bf16.f32 "
        "{%0,%1,%2,%3}, {%4,%5,%6,%7}, {%8,%9}, {%0,%1,%2,%3};"
        : "+f"(d[0]), "+f"(d[1]), "+f"(d[2]), "+f"(d[3])
        : "r"(a[0]), "r"(a[1]), "r"(a[2]), "r"(a[3]), "r"(b0), "r"(b1));
}
#define LDM4(r0, r1, r2, r3, addr) \
    asm volatile("ldmatrix.sync.aligned.m8n8.x4.shared.b16 {%0,%1,%2,%3}, [%4];" \
        : "=r"(r0), "=r"(r1), "=r"(r2), "=r"(r3) : "r"(addr))
#define CPA(dst, src) \
    asm volatile("cp.async.cg.shared.global [%0], [%1], 16;" :: "r"(dst), "l"(src))
#define CPA_WAIT() do { \
    asm volatile("cp.async.commit_group;"); \
    asm volatile("cp.async.wait_group 0;" ::: "memory"); \
} while (0)

static __device__ __forceinline__ uint32_t pack2(float a, float b) {
    return (uint32_t)__bfloat16_as_ushort(__float2bfloat16(a)) |
           ((uint32_t)__bfloat16_as_ushort(__float2bfloat16(b)) << 16);
}

// ---------------- prep: weights -> bf16 hi/lo, zero BN partial sums --------
__global__ void prep_kernel(const float* __restrict__ W1, const float* __restrict__ W2) {
    int i = blockIdx.x * 256 + threadIdx.x;
    if (i < CMID * CIN) {
        float w = W1[i];
        __nv_bfloat16 h = __float2bfloat16(w);
        g_W1h[i] = h;
        g_W1l[i] = __float2bfloat16(w - __bfloat162float(h));
    }
    if (i < COUT * CMID) {
        float w = W2[i];
        __nv_bfloat16 h = __float2bfloat16(w);
        g_W2h[i] = h;
        g_W2l[i] = __float2bfloat16(w - __bfloat162float(h));
    }
    if (i < 256) { g_s1[i] = 0.f; g_ss1[i] = 0.f; g_s2[i] = 0.f; g_ss2[i] = 0.f; }
}

// ---------------- transpose feature2 [B,256,2048] -> fp32 [B,2048,256] -----
__global__ void transpose_f2_kernel(const float* __restrict__ f2) {
    __shared__ float tile[32][33];
    int b  = blockIdx.z;
    int s0 = blockIdx.x * 32, d0 = blockIdx.y * 32;
    const float* src = f2 + (size_t)b * D2 * SPTS;
    #pragma unroll
    for (int i = 0; i < 32; i += 8)
        tile[threadIdx.y + i][threadIdx.x] =
            src[(size_t)(d0 + threadIdx.y + i) * SPTS + s0 + threadIdx.x];
    __syncthreads();
    float* dst = g_f2t + (size_t)b * SPTS * D2;
    #pragma unroll
    for (int i = 0; i < 32; i += 8)
        dst[(size_t)(s0 + threadIdx.y + i) * D2 + d0 + threadIdx.x] =
            tile[threadIdx.x][threadIdx.y + i];
}

// ---------------- copy feature1 -> feat cols [256,384) as bf16 hi/lo -------
__global__ void copy_f1_kernel(const float* __restrict__ f1) {
    __shared__ float tile[32][33];
    int b  = blockIdx.z;
    int n0 = blockIdx.x * 32, d0 = blockIdx.y * 32;
    const float* src = f1 + (size_t)b * D1 * NPTS;
    #pragma unroll
    for (int i = 0; i < 32; i += 8)
        tile[threadIdx.y + i][threadIdx.x] =
            src[(size_t)(d0 + threadIdx.y + i) * NPTS + n0 + threadIdx.x];
    __syncthreads();
    #pragma unroll
    for (int i = 0; i < 32; i += 8) {
        float v = tile[threadIdx.x][threadIdx.y + i];
        size_t o = (size_t)(b * NPTS + n0 + threadIdx.y + i) * CIN + D2 + d0 + threadIdx.x;
        __nv_bfloat16 h = __float2bfloat16(v);
        g_Fh[o] = h;
        g_Fl[o] = __float2bfloat16(v - __bfloat162float(h));
    }
}

// ---------------- 3-NN ----------------
__global__ void __launch_bounds__(256) knn_kernel(const float* __restrict__ pos1,
                                                  const float* __restrict__ pos2) {
    __shared__ float sx[SPTS], sy[SPTS], sz[SPTS], sq[SPTS];
    int b = blockIdx.y;
    const float* p2 = pos2 + (size_t)b * 3 * SPTS;
    for (int i = threadIdx.x; i < SPTS; i += blockDim.x) {
        float x = p2[i], y = p2[SPTS + i], z = p2[2 * SPTS + i];
        sx[i] = x; sy[i] = y; sz[i] = z;
        sq[i] = x * x + y * y + z * z;
    }
    __syncthreads();
    int n = blockIdx.x * blockDim.x + threadIdx.x;
    const float* p1 = pos1 + (size_t)b * 3 * NPTS;
    float x = p1[n], y = p1[NPTS + n], z = p1[2 * NPTS + n];
    float sq1 = x * x + y * y + z * z;
    float b0 = 3.4e38f, b1 = 3.4e38f, b2 = 3.4e38f;
    int   i0 = 0, i1 = 0, i2 = 0;
    for (int s = 0; s < SPTS; s++) {
        float dot = x * sx[s] + y * sy[s] + z * sz[s];
        float d   = sq1 - 2.0f * dot + sq[s];
        if (d < b2) {
            if (d < b1) {
                if (d < b0) { b2 = b1; i2 = i1; b1 = b0; i1 = i0; b0 = d; i0 = s; }
                else        { b2 = b1; i2 = i1; b1 = d;  i1 = s; }
            } else          { b2 = d;  i2 = s; }
        }
    }
    float w0 = 1.0f / fmaxf(b0, 1e-10f);
    float w1 = 1.0f / fmaxf(b1, 1e-10f);
    float w2 = 1.0f / fmaxf(b2, 1e-10f);
    float ws = w0 + w1 + w2;
    int p = b * NPTS + n;
    g_w[p * 3 + 0] = w0 / ws;  g_w[p * 3 + 1] = w1 / ws;  g_w[p * 3 + 2] = w2 / ws;
    g_idx[p * 3 + 0] = i0;     g_idx[p * 3 + 1] = i1;     g_idx[p * 3 + 2] = i2;
}

// ---------------- interp: warp per point, float4 gathers -------------------
__global__ void __launch_bounds__(256) interp_kernel() {
    int p = (blockIdx.x * 256 + threadIdx.x) >> 5;
    int l = threadIdx.x & 31;
    int b = p >> 13;
    int i0 = g_idx[p * 3 + 0], i1 = g_idx[p * 3 + 1], i2 = g_idx[p * 3 + 2];
    float w0 = g_w[p * 3 + 0], w1 = g_w[p * 3 + 1], w2 = g_w[p * 3 + 2];
    const float* r0 = g_f2t + (size_t)(b * SPTS + i0) * D2 + l * 8;
    const float* r1 = g_f2t + (size_t)(b * SPTS + i1) * D2 + l * 8;
    const float* r2 = g_f2t + (size_t)(b * SPTS + i2) * D2 + l * 8;
    float4 a0 = *(const float4*)r0,       a1 = *(const float4*)(r0 + 4);
    float4 c0 = *(const float4*)r1,       c1 = *(const float4*)(r1 + 4);
    float4 e0 = *(const float4*)r2,       e1 = *(const float4*)(r2 + 4);
    float v[8];
    v[0] = w0 * a0.x + w1 * c0.x + w2 * e0.x;
    v[1] = w0 * a0.y + w1 * c0.y + w2 * e0.y;
    v[2] = w0 * a0.z + w1 * c0.z + w2 * e0.z;
    v[3] = w0 * a0.w + w1 * c0.w + w2 * e0.w;
    v[4] = w0 * a1.x + w1 * c1.x + w2 * e1.x;
    v[5] = w0 * a1.y + w1 * c1.y + w2 * e1.y;
    v[6] = w0 * a1.z + w1 * c1.z + w2 * e1.z;
    v[7] = w0 * a1.w + w1 * c1.w + w2 * e1.w;
    uint4 hv, lv;
    float lo[8];
    #pragma unroll
    for (int i = 0; i < 8; i++)
        lo[i] = v[i] - __bfloat162float(__float2bfloat16(v[i]));
    hv.x = pack2(v[0], v[1]); hv.y = pack2(v[2], v[3]);
    hv.z = pack2(v[4], v[5]); hv.w = pack2(v[6], v[7]);
    lv.x = pack2(lo[0], lo[1]); lv.y = pack2(lo[2], lo[3]);
    lv.z = pack2(lo[4], lo[5]); lv.w = pack2(lo[6], lo[7]);
    size_t o = (size_t)p * CIN + l * 8;
    *(uint4*)(g_Fh + o) = hv;
    *(uint4*)(g_Fl + o) = lv;
}

// ---------------- convert y1 -> relu(bn1(y1)) as bf16 hi/lo ----------------
__global__ void __launch_bounds__(256) convert1_kernel() {
    size_t i = (size_t)blockIdx.x * 256 + threadIdx.x;   // one float4
    int c = (int)((i * 4) & 255);
    float4 v  = ((const float4*)g_y1)[i];
    float4 Ac = *(const float4*)&g_bnA1[c];
    float4 Bc = *(const float4*)&g_bnB1[c];
    float x0 = fmaxf(v.x * Ac.x + Bc.x, 0.f);
    float x1 = fmaxf(v.y * Ac.y + Bc.y, 0.f);
    float x2 = fmaxf(v.z * Ac.z + Bc.z, 0.f);
    float x3 = fmaxf(v.w * Ac.w + Bc.w, 0.f);
    uint2 hv, lv;
    hv.x = pack2(x0, x1); hv.y = pack2(x2, x3);
    lv.x = pack2(x0 - __bfloat162float(__float2bfloat16(x0)),
                 x1 - __bfloat162float(__float2bfloat16(x1)));
    lv.y = pack2(x2 - __bfloat162float(__float2bfloat16(x2)),
                 x3 - __bfloat162float(__float2bfloat16(x3)));
    ((uint2*)g_B1h)[i] = hv;
    ((uint2*)g_B1l)[i] = lv;
}

// ---------------- split-bf16 tensor-core GEMM (ldmatrix + cp.async) --------
// MODE 0: y1 = W1 @ feat^T + b1 (K=384)   MODE 1: y2 = W2 @ B1^T + b2 (K=256)
template<int NC, int MODE>
__global__ void __launch_bounds__(256, 2) gemm_mma(const float* __restrict__ bias) {
    extern __shared__ __align__(16) char sm[];
    int tid = threadIdx.x;
    int w   = tid >> 5, l = tid & 31;
    int mw  = (w >> 2) * 64;
    int nw  = (w & 3) * 32;
    int m0  = blockIdx.y * TM;
    int p0  = blockIdx.x * TN;
    const int AK = NC * KC;

    const __nv_bfloat16* Ah_src = (MODE == 0) ? g_W1h : g_W2h;
    const __nv_bfloat16* Al_src = (MODE == 0) ? g_W1l : g_W2l;
    const __nv_bfloat16* Bh_src = (MODE == 0) ? g_Fh  : g_B1h;
    const __nv_bfloat16* Bl_src = (MODE == 0) ? g_Fl  : g_B1l;

    uint32_t smb = smem_u32(sm);
    // per-lane ldmatrix offsets
    uint32_t aoff = smb + (uint32_t)(mw + (l & 15)) * ROWB + ((l >> 4) * 16);
    uint32_t boff = smb + (uint32_t)(nw + (l & 7) + ((l >> 4) << 3)) * ROWB + (((l >> 3) & 1) * 16);
    // per-thread staging offsets (4 segs/thread/tile)
    int sr = tid >> 3, ssc = tid & 7;
    uint32_t stoff = smb + (uint32_t)sr * ROWB + ssc * 16;

    float acc[4][4][4] = {};

    for (int c = 0; c < NC; ++c) {
        int kc = c * KC;
        if (c) __syncthreads();
        #pragma unroll
        for (int i = 0; i < 4; i++) {
            int r = sr + i * 32;
            uint32_t d = stoff + i * 32 * ROWB;
            const __nv_bfloat16* ga = Ah_src + (size_t)(m0 + r) * AK + kc + ssc * 8;
            const __nv_bfloat16* gl = Al_src + (size_t)(m0 + r) * AK + kc + ssc * 8;
            const __nv_bfloat16* gb = Bh_src + (size_t)(p0 + r) * AK + kc + ssc * 8;
            const __nv_bfloat16* gc = Bl_src + (size_t)(p0 + r) * AK + kc + ssc * 8;
            CPA(d + OFF_AH, ga);
            CPA(d + OFF_AL, gl);
            CPA(d + OFF_BH, gb);
            CPA(d + OFF_BL, gc);
        }
        CPA_WAIT();
        __syncthreads();
        #pragma unroll
        for (int kk = 0; kk < 4; kk++) {
            uint32_t ka = aoff + kk * 32;
            uint32_t kb = boff + kk * 32;
            uint32_t ah[4][4], al[4][4], bh[4][2], bl[4][2];
            #pragma unroll
            for (int mi = 0; mi < 4; mi++) {
                LDM4(ah[mi][0], ah[mi][1], ah[mi][2], ah[mi][3], ka + OFF_AH + mi * (16 * ROWB));
                LDM4(al[mi][0], al[mi][1], al[mi][2], al[mi][3], ka + OFF_AL + mi * (16 * ROWB));
            }
            LDM4(bh[0][0], bh[0][1], bh[1][0], bh[1][1], kb + OFF_BH);
            LDM4(bh[2][0], bh[2][1], bh[3][0], bh[3][1], kb + OFF_BH + 16 * ROWB);
            LDM4(bl[0][0], bl[0][1], bl[1][0], bl[1][1], kb + OFF_BL);
            LDM4(bl[2][0], bl[2][1], bl[3][0], bl[3][1], kb + OFF_BL + 16 * ROWB);
            #pragma unroll
            for (int ni = 0; ni < 4; ni++)
                #pragma unroll
                for (int mi = 0; mi < 4; mi++) {
                    mma16816(acc[mi][ni], ah[mi], bh[ni][0], bh[ni][1]);
                    mma16816(acc[mi][ni], ah[mi], bl[ni][0], bl[ni][1]);
                    mma16816(acc[mi][ni], al[mi], bh[ni][0], bh[ni][1]);
                }
        }
    }

    // --- epilogue: acc -> SMEM tile [128p][132c], stats + coalesced write --
    __syncthreads();
    float* tile = (float*)sm;
    #pragma unroll
    for (int mi = 0; mi < 4; mi++) {
        int c_ = mw + mi * 16 + (l >> 2);
        #pragma unroll
        for (int ni = 0; ni < 4; ni++) {
            int p_ = nw + ni * 8 + (l & 3) * 2;
            tile[p_ * 132 + c_]            = acc[mi][ni][0];
            tile[(p_ + 1) * 132 + c_]      = acc[mi][ni][1];
            tile[p_ * 132 + c_ + 8]        = acc[mi][ni][2];
            tile[(p_ + 1) * 132 + c_ + 8]  = acc[mi][ni][3];
        }
    }
    __syncthreads();

    float* ydst = (MODE == 0) ? g_y1 : g_y2;
    float* gs   = (MODE == 0) ? g_s1 : g_s2;
    float* gss  = (MODE == 0) ? g_ss1 : g_ss2;
    {
        int c = tid & 127;
        int r0 = (tid >> 7) * 64;
        float bi = bias[m0 + c];
        float s = 0.f, s2 = 0.f;
        #pragma unroll 4
        for (int p = 0; p < 64; p++) {
            float v = tile[(r0 + p) * 132 + c] + bi;
            s += v; s2 += v * v;
        }
        atomicAdd(&gs[m0 + c], s);
        atomicAdd(&gss[m0 + c], s2);
    }
    #pragma unroll
    for (int i = 0; i < 16; i++) {
        int t = i * 256 + tid;
        int p = t >> 5, g = t & 31;
        float4 v  = *(const float4*)&tile[p * 132 + g * 4];
        float4 bb = *(const float4*)&bias[m0 + g * 4];
        v.x += bb.x; v.y += bb.y; v.z += bb.z; v.w += bb.w;
        *(float4*)&ydst[(size_t)(p0 + p) * 256 + m0 + g * 4] = v;
    }
}

// ---------------- BN finalize ----------------
__global__ void bnfin_kernel(int which, const float* __restrict__ g,
                             const float* __restrict__ beta) {
    int c = threadIdx.x;
    float s  = which ? g_s2[c]  : g_s1[c];
    float ss = which ? g_ss2[c] : g_ss1[c];
    float mean = s / (float)PTOT;
    float var  = ss / (float)PTOT - mean * mean;
    float A = g[c] * rsqrtf(var + 1e-5f);
    float B = beta[c] - mean * A;
    if (which) { g_bnA2[c] = A; g_bnB2[c] = B; }
    else       { g_bnA1[c] = A; g_bnB1[c] = B; }
}

// ---------------- final: BN2+ReLU + transpose [P,256] -> out [B,256,N] -----
__global__ void final_kernel(float* __restrict__ out) {
    __shared__ float tile[32][33];
    int p0 = blockIdx.x * 32, c0 = blockIdx.y * 32;
    int tx = threadIdx.x, ty = threadIdx.y;
    int c = c0 + tx;
    float A = g_bnA2[c], B = g_bnB2[c];
    #pragma unroll
    for (int i = 0; i < 32; i += 8) {
        float v = g_y2[(size_t)(p0 + ty + i) * 256 + c];
        tile[ty + i][tx] = fmaxf(v * A + B, 0.f);
    }
    __syncthreads();
    int b = p0 >> 13;
    int n0 = p0 & (NPTS - 1);
    #pragma unroll
    for (int i = 0; i < 32; i += 8)
        out[(size_t)b * COUT * NPTS + (size_t)(c0 + ty + i) * NPTS + n0 + tx] =
            tile[tx][ty + i];
}

// ---------------------------------------------------------------------------
extern "C" void kernel_launch(void* const* d_in, const int* in_sizes, int n_in,
                              void* d_out, int out_size) {
    const float* pos1  = (const float*)d_in[0];
    const float* pos2  = (const float*)d_in[1];
    const float* feat1 = (const float*)d_in[2];
    const float* feat2 = (const float*)d_in[3];
    const float* W1    = (const float*)d_in[4];
    const float* b1    = (const float*)d_in[5];
    const float* g1    = (const float*)d_in[6];
    const float* be1   = (const float*)d_in[7];
    const float* W2    = (const float*)d_in[8];
    const float* b2    = (const float*)d_in[9];
    const float* g2    = (const float*)d_in[10];
    const float* be2   = (const float*)d_in[11];
    float* out = (float*)d_out;

    cudaFuncSetAttribute(gemm_mma<6, 0>, cudaFuncAttributeMaxDynamicSharedMemorySize, SMEM_DYN);
    cudaFuncSetAttribute(gemm_mma<4, 1>, cudaFuncAttributeMaxDynamicSharedMemorySize, SMEM_DYN);

    prep_kernel<<<(CMID * CIN + 255) / 256, 256>>>(W1, W2);
    transpose_f2_kernel<<<dim3(SPTS / 32, D2 / 32, BATCH), dim3(32, 8)>>>(feat2);
    knn_kernel<<<dim3(NPTS / 256, BATCH), 256>>>(pos1, pos2);
    interp_kernel<<<PTOT / 8, 256>>>();
    copy_f1_kernel<<<dim3(NPTS / 32, D1 / 32, BATCH), dim3(32, 8)>>>(feat1);
    gemm_mma<6, 0><<<dim3(PTOT / TN, CMID / TM), 256, SMEM_DYN>>>(b1);
    bnfin_kernel<<<1, 256>>>(0, g1, be1);
    convert1_kernel<<<PTOT * CMID / 4 / 256, 256>>>();
    gemm_mma<4, 1><<<dim3(PTOT / TN, COUT / TM), 256, SMEM_DYN>>>(b2);
    bnfin_kernel<<<1, 256>>>(1, g2, be2);
    final_kernel<<<dim3(PTOT / 32, COUT / 32), dim3(32, 8)>>>(out);
}